// round 2
// baseline (speedup 1.0000x reference)
#include <cuda_runtime.h>
#include <math.h>

#define W_IMG 1024
#define N_PIX (W_IMG * W_IMG)
#define ROWS 16          // rows per warp
#define WARPS 8
#define NTH 256
#define MAXB 8

// stats per batch: [0..2]=sum q_c^2, [3..5]=sum k_c^2, [6..14]=sum q_c*k_d
__device__ float g_stats[MAXB][16];
__device__ float g_M[MAXB][12];

__global__ void k_zero() {
    int i = threadIdx.x;
    if (i < MAXB * 16) ((float*)g_stats)[i] = 0.0f;
}

__global__ __launch_bounds__(NTH) void k_stats(const float* __restrict__ x,
                                               const float* __restrict__ fhigh,
                                               const float* __restrict__ qC,
                                               const float* __restrict__ qD,
                                               const float* __restrict__ kC,
                                               const float* __restrict__ kD) {
    __shared__ float red[WARPS][15];

    const int b = blockIdx.z;
    const int warp = threadIdx.x >> 5, lane = threadIdx.x & 31;
    const int gxb = blockIdx.x * 32;
    const int gx = gxb + lane;
    const int y0 = (blockIdx.y * WARPS + warp) * ROWS;

    const float* __restrict__ xb = x + (size_t)b * 3 * N_PIX;
    const float* __restrict__ fb = fhigh + (size_t)b * 3 * N_PIX;

    float cq[9], ck[9], dq[27], dk[27];
#pragma unroll
    for (int i = 0; i < 9; i++) { cq[i] = qC[i]; ck[i] = kC[i]; }
#pragma unroll
    for (int i = 0; i < 27; i++) { dq[i] = qD[i]; dk[i] = kD[i]; }

    float aq0[3], aq1[3], aq2[3], ak0[3], ak1[3], ak2[3];
#pragma unroll
    for (int c = 0; c < 3; c++) {
        aq0[c] = aq1[c] = aq2[c] = 0.f;
        ak0[c] = ak1[c] = ak2[c] = 0.f;
    }
    float p[15];
#pragma unroll
    for (int i = 0; i < 15; i++) p[i] = 0.f;

    const bool is_edge = (lane == 0) | (lane == 31);
    const int nx = (lane == 0) ? gxb - 1 : gxb + 32;
    const bool nx_ok = (unsigned)nx < (unsigned)W_IMG;

#pragma unroll 3
    for (int iy = 0; iy < ROWS + 2; ++iy) {
        int yin = y0 + iy - 1;
        bool yok = (unsigned)yin < (unsigned)W_IMG;

        float qm[3] = {0.f, 0.f, 0.f}, km[3] = {0.f, 0.f, 0.f};
        if (yok) {
            size_t o = (size_t)yin * W_IMG + gx;
            float f0 = fb[o], f1 = fb[o + N_PIX], f2 = fb[o + 2 * N_PIX];
            qm[0] = cq[0] * f0 + cq[1] * f1 + cq[2] * f2;
            qm[1] = cq[3] * f0 + cq[4] * f1 + cq[5] * f2;
            qm[2] = cq[6] * f0 + cq[7] * f1 + cq[8] * f2;
            const float* px = xb + o * 3;
            float g0 = px[0], g1 = px[1], g2 = px[2];
            km[0] = ck[0] * g0 + ck[1] * g1 + ck[2] * g2;
            km[1] = ck[3] * g0 + ck[4] * g1 + ck[5] * g2;
            km[2] = ck[6] * g0 + ck[7] * g1 + ck[8] * g2;
        }
        float qe[3] = {0.f, 0.f, 0.f}, ke[3] = {0.f, 0.f, 0.f};
        if (yok && is_edge && nx_ok) {
            size_t o = (size_t)yin * W_IMG + nx;
            float f0 = fb[o], f1 = fb[o + N_PIX], f2 = fb[o + 2 * N_PIX];
            qe[0] = cq[0] * f0 + cq[1] * f1 + cq[2] * f2;
            qe[1] = cq[3] * f0 + cq[4] * f1 + cq[5] * f2;
            qe[2] = cq[6] * f0 + cq[7] * f1 + cq[8] * f2;
            const float* px = xb + o * 3;
            float g0 = px[0], g1 = px[1], g2 = px[2];
            ke[0] = ck[0] * g0 + ck[1] * g1 + ck[2] * g2;
            ke[1] = ck[3] * g0 + ck[4] * g1 + ck[5] * g2;
            ke[2] = ck[6] * g0 + ck[7] * g1 + ck[8] * g2;
        }

#pragma unroll
        for (int c = 0; c < 3; c++) {
            float ql = __shfl_up_sync(0xffffffffu, qm[c], 1);
            float qr = __shfl_down_sync(0xffffffffu, qm[c], 1);
            if (lane == 0) ql = qe[c];
            if (lane == 31) qr = qe[c];
            float kl = __shfl_up_sync(0xffffffffu, km[c], 1);
            float kr = __shfl_down_sync(0xffffffffu, km[c], 1);
            if (lane == 0) kl = ke[c];
            if (lane == 31) kr = ke[c];

            aq0[c] += dq[c * 9 + 6] * ql + dq[c * 9 + 7] * qm[c] + dq[c * 9 + 8] * qr;
            aq1[c] += dq[c * 9 + 3] * ql + dq[c * 9 + 4] * qm[c] + dq[c * 9 + 5] * qr;
            aq2[c] += dq[c * 9 + 0] * ql + dq[c * 9 + 1] * qm[c] + dq[c * 9 + 2] * qr;
            ak0[c] += dk[c * 9 + 6] * kl + dk[c * 9 + 7] * km[c] + dk[c * 9 + 8] * kr;
            ak1[c] += dk[c * 9 + 3] * kl + dk[c * 9 + 4] * km[c] + dk[c * 9 + 5] * kr;
            ak2[c] += dk[c * 9 + 0] * kl + dk[c * 9 + 1] * km[c] + dk[c * 9 + 2] * kr;
        }

        if (iy >= 2) {
            p[0] += aq0[0] * aq0[0];
            p[1] += aq0[1] * aq0[1];
            p[2] += aq0[2] * aq0[2];
            p[3] += ak0[0] * ak0[0];
            p[4] += ak0[1] * ak0[1];
            p[5] += ak0[2] * ak0[2];
#pragma unroll
            for (int c = 0; c < 3; c++)
#pragma unroll
                for (int d = 0; d < 3; d++)
                    p[6 + c * 3 + d] += aq0[c] * ak0[d];
        }
#pragma unroll
        for (int c = 0; c < 3; c++) {
            aq0[c] = aq1[c]; aq1[c] = aq2[c]; aq2[c] = 0.f;
            ak0[c] = ak1[c]; ak1[c] = ak2[c]; ak2[c] = 0.f;
        }
    }

    // warp reduce
#pragma unroll
    for (int i = 0; i < 15; i++)
#pragma unroll
        for (int o = 16; o; o >>= 1)
            p[i] += __shfl_down_sync(0xffffffffu, p[i], o);
    if (lane == 0) {
#pragma unroll
        for (int i = 0; i < 15; i++) red[warp][i] = p[i];
    }
    __syncthreads();
    if (threadIdx.x < 15) {
        float t = 0.f;
#pragma unroll
        for (int w2 = 0; w2 < WARPS; w2++) t += red[w2][threadIdx.x];
        atomicAdd(&g_stats[b][threadIdx.x], t);
    }
}

__global__ void k_attn(const float* __restrict__ proj_w,
                       const float* __restrict__ temp, int B) {
    if (threadIdx.x != 0 || blockIdx.x != 0) return;
    float T = temp[0];
    for (int b = 0; b < B; b++) {
        float nq[3], nk[3];
#pragma unroll
        for (int c = 0; c < 3; c++) {
            nq[c] = fmaxf(sqrtf(g_stats[b][c]), 1e-12f);
            nk[c] = fmaxf(sqrtf(g_stats[b][3 + c]), 1e-12f);
        }
        float a[3][3];
#pragma unroll
        for (int c = 0; c < 3; c++)
#pragma unroll
            for (int d = 0; d < 3; d++)
                a[c][d] = g_stats[b][6 + c * 3 + d] / (nq[c] * nk[d]) * T;
#pragma unroll
        for (int c = 0; c < 3; c++) {
            float mx = fmaxf(a[c][0], fmaxf(a[c][1], a[c][2]));
            float e0 = expf(a[c][0] - mx);
            float e1 = expf(a[c][1] - mx);
            float e2 = expf(a[c][2] - mx);
            float inv = 1.f / (e0 + e1 + e2);
            a[c][0] = e0 * inv; a[c][1] = e1 * inv; a[c][2] = e2 * inv;
        }
#pragma unroll
        for (int co = 0; co < 3; co++)
#pragma unroll
            for (int d = 0; d < 3; d++) {
                float m = 0.f;
#pragma unroll
                for (int c = 0; c < 3; c++) m += proj_w[co * 3 + c] * a[c][d];
                g_M[b][co * 3 + d] = m;
            }
    }
}

__global__ __launch_bounds__(NTH) void k_out(const float* __restrict__ x,
                                             const float* __restrict__ kC,
                                             const float* __restrict__ kD,
                                             const float* __restrict__ proj_b,
                                             float* __restrict__ out) {
    const int b = blockIdx.z;
    const int warp = threadIdx.x >> 5, lane = threadIdx.x & 31;
    const int gxb = blockIdx.x * 32;
    const int gx = gxb + lane;
    const int y0 = (blockIdx.y * WARPS + warp) * ROWS;

    const float* __restrict__ xb = x + (size_t)b * 3 * N_PIX;

    float ck[9], dk[27];
#pragma unroll
    for (int i = 0; i < 9; i++) ck[i] = kC[i];
#pragma unroll
    for (int i = 0; i < 27; i++) dk[i] = kD[i];

    float m[9];
#pragma unroll
    for (int i = 0; i < 9; i++) m[i] = g_M[b][i];
    const float b0 = proj_b[0], b1 = proj_b[1], b2 = proj_b[2];

    float ak0[3], ak1[3], ak2[3];
#pragma unroll
    for (int c = 0; c < 3; c++) { ak0[c] = ak1[c] = ak2[c] = 0.f; }

    const bool is_edge = (lane == 0) | (lane == 31);
    const int nx = (lane == 0) ? gxb - 1 : gxb + 32;
    const bool nx_ok = (unsigned)nx < (unsigned)W_IMG;

#pragma unroll 3
    for (int iy = 0; iy < ROWS + 2; ++iy) {
        int yin = y0 + iy - 1;
        bool yok = (unsigned)yin < (unsigned)W_IMG;

        float km[3] = {0.f, 0.f, 0.f};
        if (yok) {
            size_t o = (size_t)yin * W_IMG + gx;
            const float* px = xb + o * 3;
            float g0 = px[0], g1 = px[1], g2 = px[2];
            km[0] = ck[0] * g0 + ck[1] * g1 + ck[2] * g2;
            km[1] = ck[3] * g0 + ck[4] * g1 + ck[5] * g2;
            km[2] = ck[6] * g0 + ck[7] * g1 + ck[8] * g2;
        }
        float ke[3] = {0.f, 0.f, 0.f};
        if (yok && is_edge && nx_ok) {
            size_t o = (size_t)yin * W_IMG + nx;
            const float* px = xb + o * 3;
            float g0 = px[0], g1 = px[1], g2 = px[2];
            ke[0] = ck[0] * g0 + ck[1] * g1 + ck[2] * g2;
            ke[1] = ck[3] * g0 + ck[4] * g1 + ck[5] * g2;
            ke[2] = ck[6] * g0 + ck[7] * g1 + ck[8] * g2;
        }

#pragma unroll
        for (int c = 0; c < 3; c++) {
            float kl = __shfl_up_sync(0xffffffffu, km[c], 1);
            float kr = __shfl_down_sync(0xffffffffu, km[c], 1);
            if (lane == 0) kl = ke[c];
            if (lane == 31) kr = ke[c];

            ak0[c] += dk[c * 9 + 6] * kl + dk[c * 9 + 7] * km[c] + dk[c * 9 + 8] * kr;
            ak1[c] += dk[c * 9 + 3] * kl + dk[c * 9 + 4] * km[c] + dk[c * 9 + 5] * kr;
            ak2[c] += dk[c * 9 + 0] * kl + dk[c * 9 + 1] * km[c] + dk[c * 9 + 2] * kr;
        }

        if (iy >= 2) {
            int yout = y0 + iy - 2;
            float k0 = ak0[0], k1 = ak0[1], k2 = ak0[2];
            size_t o = ((size_t)b * N_PIX + (size_t)yout * W_IMG + gx) * 3;
            out[o + 0] = m[0] * k0 + m[1] * k1 + m[2] * k2 + b0;
            out[o + 1] = m[3] * k0 + m[4] * k1 + m[5] * k2 + b1;
            out[o + 2] = m[6] * k0 + m[7] * k1 + m[8] * k2 + b2;
        }
#pragma unroll
        for (int c = 0; c < 3; c++) {
            ak0[c] = ak1[c]; ak1[c] = ak2[c]; ak2[c] = 0.f;
        }
    }
}

extern "C" void kernel_launch(void* const* d_in, const int* in_sizes, int n_in,
                              void* d_out, int out_size) {
    const float* x     = (const float*)d_in[0];
    const float* fhigh = (const float*)d_in[1];
    const float* qCw   = (const float*)d_in[2];
    const float* qdw   = (const float*)d_in[3];
    const float* kCw   = (const float*)d_in[4];
    const float* kdw   = (const float*)d_in[5];
    const float* projw = (const float*)d_in[6];
    const float* projb = (const float*)d_in[7];
    const float* temp  = (const float*)d_in[8];
    float* out = (float*)d_out;

    int B = in_sizes[0] / (N_PIX * 3);
    if (B > MAXB) B = MAXB;

    k_zero<<<1, 128>>>();
    dim3 grid(W_IMG / 32, W_IMG / (WARPS * ROWS), B);
    k_stats<<<grid, NTH>>>(x, fhigh, qCw, qdw, kCw, kdw);
    k_attn<<<1, 1>>>(projw, temp, B);
    k_out<<<grid, NTH>>>(x, kCw, kdw, projb, out);
}

// round 4
// speedup vs baseline: 1.8571x; 1.8571x over previous
#include <cuda_runtime.h>
#include <math.h>

#define W_IMG 1024
#define N_PIX (W_IMG * W_IMG)
#define MAXB 8
#define NTH 256

// stats per batch: [0..2]=sum q_c^2, [3..5]=sum k_c^2, [6..14]=sum q_c*k_d
__device__ float g_stats[MAXB][16];
__device__ float g_M[MAXB][12];

__global__ void k_zero() {
    int i = threadIdx.x;
    if (i < MAXB * 16) ((float*)g_stats)[i] = 0.0f;
}

// ---------------------------------------------------------------------------
// k_stats: 4x4 patch per thread. K path first (store k patch), then Q path
// accumulating the 15 per-batch statistics on the fly.
// ---------------------------------------------------------------------------
__global__ __launch_bounds__(NTH) void k_stats(const float* __restrict__ x,
                                               const float* __restrict__ fhigh,
                                               const float* __restrict__ qC,
                                               const float* __restrict__ qD,
                                               const float* __restrict__ kC,
                                               const float* __restrict__ kD) {
    __shared__ float red[NTH / 32][15];

    const int b = blockIdx.z;
    const int warp = threadIdx.x >> 5, lane = threadIdx.x & 31;
    const int wx0 = blockIdx.x * 128;           // warp x range [wx0, wx0+128)
    const int px0 = wx0 + lane * 4;             // this thread's 4 pixels
    const int y0 = blockIdx.y * 32 + warp * 4;  // 4 output rows

    const float* __restrict__ xb = x + (size_t)b * 3 * N_PIX;
    const float* __restrict__ fb = fhigh + (size_t)b * 3 * N_PIX;

    const bool is_e = (lane == 0) | (lane == 31);
    const int ex = (lane == 0) ? wx0 - 1 : wx0 + 128;
    const bool ex_ok = (unsigned)ex < (unsigned)W_IMG;

    float p[15];
#pragma unroll
    for (int i = 0; i < 15; i++) p[i] = 0.f;

    float kout[3][4][4];  // [ch][row][j]

    // ================= K path (input x, channels-last) =================
    {
        float cw[9], dw[27];
#pragma unroll
        for (int i = 0; i < 9; i++) cw[i] = kC[i];
#pragma unroll
        for (int i = 0; i < 27; i++) dw[i] = kD[i];

        float a0[3][4], a1[3][4], a2[3][4];
#pragma unroll
        for (int c = 0; c < 3; c++)
#pragma unroll
            for (int j = 0; j < 4; j++) { a0[c][j] = a1[c][j] = a2[c][j] = 0.f; }

#pragma unroll
        for (int iy = 0; iy < 6; iy++) {
            const int yin = y0 + iy - 1;
            const bool yok = (unsigned)yin < (unsigned)W_IMG;

            float hm[3][4];
#pragma unroll
            for (int c = 0; c < 3; c++)
#pragma unroll
                for (int j = 0; j < 4; j++) hm[c][j] = 0.f;

            if (yok) {
                const float4* p4 = (const float4*)(xb + (size_t)(yin * W_IMG + px0) * 3);
                float4 v0 = p4[0], v1 = p4[1], v2 = p4[2];
                float g[4][3] = {{v0.x, v0.y, v0.z}, {v0.w, v1.x, v1.y},
                                 {v1.z, v1.w, v2.x}, {v2.y, v2.z, v2.w}};
#pragma unroll
                for (int j = 0; j < 4; j++)
#pragma unroll
                    for (int c = 0; c < 3; c++)
                        hm[c][j] = cw[c * 3] * g[j][0] + cw[c * 3 + 1] * g[j][1] + cw[c * 3 + 2] * g[j][2];
            }
            float he[3] = {0.f, 0.f, 0.f};
            if (yok && is_e && ex_ok) {
                const float* pe = xb + (size_t)(yin * W_IMG + ex) * 3;
                float g0 = pe[0], g1 = pe[1], g2 = pe[2];
#pragma unroll
                for (int c = 0; c < 3; c++)
                    he[c] = cw[c * 3] * g0 + cw[c * 3 + 1] * g1 + cw[c * 3 + 2] * g2;
            }
            float hl[3], hr[3];
#pragma unroll
            for (int c = 0; c < 3; c++) {
                hl[c] = __shfl_up_sync(0xffffffffu, hm[c][3], 1);
                hr[c] = __shfl_down_sync(0xffffffffu, hm[c][0], 1);
                if (lane == 0) hl[c] = he[c];
                if (lane == 31) hr[c] = he[c];
            }
#pragma unroll
            for (int c = 0; c < 3; c++)
#pragma unroll
                for (int j = 0; j < 4; j++) {
                    float L = j ? hm[c][j - 1] : hl[c];
                    float M_ = hm[c][j];
                    float R = (j < 3) ? hm[c][j + 1] : hr[c];
                    a0[c][j] += dw[c * 9 + 6] * L + dw[c * 9 + 7] * M_ + dw[c * 9 + 8] * R;
                    a1[c][j] += dw[c * 9 + 3] * L + dw[c * 9 + 4] * M_ + dw[c * 9 + 5] * R;
                    a2[c][j] += dw[c * 9 + 0] * L + dw[c * 9 + 1] * M_ + dw[c * 9 + 2] * R;
                }
            if (iy >= 2) {
                const int r = iy - 2;
#pragma unroll
                for (int c = 0; c < 3; c++)
#pragma unroll
                    for (int j = 0; j < 4; j++) {
                        float v = a0[c][j];
                        kout[c][r][j] = v;
                        p[3 + c] += v * v;
                    }
            }
            // rotate EVERY input row (bug in R3: this was inside iy>=2)
#pragma unroll
            for (int c = 0; c < 3; c++)
#pragma unroll
                for (int j = 0; j < 4; j++) {
                    a0[c][j] = a1[c][j];
                    a1[c][j] = a2[c][j];
                    a2[c][j] = 0.f;
                }
        }
    }

    // ================= Q path (input fhigh, planar) =================
    {
        float cw[9], dw[27];
#pragma unroll
        for (int i = 0; i < 9; i++) cw[i] = qC[i];
#pragma unroll
        for (int i = 0; i < 27; i++) dw[i] = qD[i];

        float a0[3][4], a1[3][4], a2[3][4];
#pragma unroll
        for (int c = 0; c < 3; c++)
#pragma unroll
            for (int j = 0; j < 4; j++) { a0[c][j] = a1[c][j] = a2[c][j] = 0.f; }

#pragma unroll
        for (int iy = 0; iy < 6; iy++) {
            const int yin = y0 + iy - 1;
            const bool yok = (unsigned)yin < (unsigned)W_IMG;

            float hm[3][4];
#pragma unroll
            for (int c = 0; c < 3; c++)
#pragma unroll
                for (int j = 0; j < 4; j++) hm[c][j] = 0.f;

            if (yok) {
                const size_t o = (size_t)yin * W_IMG + px0;
                float4 f0 = *(const float4*)(fb + o);
                float4 f1 = *(const float4*)(fb + o + N_PIX);
                float4 f2 = *(const float4*)(fb + o + 2 * N_PIX);
                float g[4][3] = {{f0.x, f1.x, f2.x}, {f0.y, f1.y, f2.y},
                                 {f0.z, f1.z, f2.z}, {f0.w, f1.w, f2.w}};
#pragma unroll
                for (int j = 0; j < 4; j++)
#pragma unroll
                    for (int c = 0; c < 3; c++)
                        hm[c][j] = cw[c * 3] * g[j][0] + cw[c * 3 + 1] * g[j][1] + cw[c * 3 + 2] * g[j][2];
            }
            float he[3] = {0.f, 0.f, 0.f};
            if (yok && is_e && ex_ok) {
                const size_t o = (size_t)yin * W_IMG + ex;
                float g0 = fb[o], g1 = fb[o + N_PIX], g2 = fb[o + 2 * N_PIX];
#pragma unroll
                for (int c = 0; c < 3; c++)
                    he[c] = cw[c * 3] * g0 + cw[c * 3 + 1] * g1 + cw[c * 3 + 2] * g2;
            }
            float hl[3], hr[3];
#pragma unroll
            for (int c = 0; c < 3; c++) {
                hl[c] = __shfl_up_sync(0xffffffffu, hm[c][3], 1);
                hr[c] = __shfl_down_sync(0xffffffffu, hm[c][0], 1);
                if (lane == 0) hl[c] = he[c];
                if (lane == 31) hr[c] = he[c];
            }
#pragma unroll
            for (int c = 0; c < 3; c++)
#pragma unroll
                for (int j = 0; j < 4; j++) {
                    float L = j ? hm[c][j - 1] : hl[c];
                    float M_ = hm[c][j];
                    float R = (j < 3) ? hm[c][j + 1] : hr[c];
                    a0[c][j] += dw[c * 9 + 6] * L + dw[c * 9 + 7] * M_ + dw[c * 9 + 8] * R;
                    a1[c][j] += dw[c * 9 + 3] * L + dw[c * 9 + 4] * M_ + dw[c * 9 + 5] * R;
                    a2[c][j] += dw[c * 9 + 0] * L + dw[c * 9 + 1] * M_ + dw[c * 9 + 2] * R;
                }
            if (iy >= 2) {
                const int r = iy - 2;
#pragma unroll
                for (int c = 0; c < 3; c++)
#pragma unroll
                    for (int j = 0; j < 4; j++) {
                        float q = a0[c][j];
                        p[c] += q * q;
#pragma unroll
                        for (int d = 0; d < 3; d++)
                            p[6 + c * 3 + d] += q * kout[d][r][j];
                    }
            }
#pragma unroll
            for (int c = 0; c < 3; c++)
#pragma unroll
                for (int j = 0; j < 4; j++) {
                    a0[c][j] = a1[c][j];
                    a1[c][j] = a2[c][j];
                    a2[c][j] = 0.f;
                }
        }
    }

    // reduce
#pragma unroll
    for (int i = 0; i < 15; i++)
#pragma unroll
        for (int o = 16; o; o >>= 1)
            p[i] += __shfl_down_sync(0xffffffffu, p[i], o);
    if (lane == 0) {
#pragma unroll
        for (int i = 0; i < 15; i++) red[warp][i] = p[i];
    }
    __syncthreads();
    if (threadIdx.x < 15) {
        float t = 0.f;
#pragma unroll
        for (int w2 = 0; w2 < NTH / 32; w2++) t += red[w2][threadIdx.x];
        atomicAdd(&g_stats[b][threadIdx.x], t);
    }
}

__global__ void k_attn(const float* __restrict__ proj_w,
                       const float* __restrict__ temp, int B) {
    if (threadIdx.x != 0 || blockIdx.x != 0) return;
    float T = temp[0];
    for (int b = 0; b < B; b++) {
        float nq[3], nk[3];
#pragma unroll
        for (int c = 0; c < 3; c++) {
            nq[c] = fmaxf(sqrtf(g_stats[b][c]), 1e-12f);
            nk[c] = fmaxf(sqrtf(g_stats[b][3 + c]), 1e-12f);
        }
        float a[3][3];
#pragma unroll
        for (int c = 0; c < 3; c++)
#pragma unroll
            for (int d = 0; d < 3; d++)
                a[c][d] = g_stats[b][6 + c * 3 + d] / (nq[c] * nk[d]) * T;
#pragma unroll
        for (int c = 0; c < 3; c++) {
            float mx = fmaxf(a[c][0], fmaxf(a[c][1], a[c][2]));
            float e0 = expf(a[c][0] - mx);
            float e1 = expf(a[c][1] - mx);
            float e2 = expf(a[c][2] - mx);
            float inv = 1.f / (e0 + e1 + e2);
            a[c][0] = e0 * inv; a[c][1] = e1 * inv; a[c][2] = e2 * inv;
        }
#pragma unroll
        for (int co = 0; co < 3; co++)
#pragma unroll
            for (int d = 0; d < 3; d++) {
                float m = 0.f;
#pragma unroll
                for (int c = 0; c < 3; c++) m += proj_w[co * 3 + c] * a[c][d];
                g_M[b][co * 3 + d] = m;
            }
    }
}

// ---------------------------------------------------------------------------
// k_out: 4x4 patch per thread, k path only, apply M + bias, float4 stores.
// ---------------------------------------------------------------------------
__global__ __launch_bounds__(NTH) void k_out(const float* __restrict__ x,
                                             const float* __restrict__ kC,
                                             const float* __restrict__ kD,
                                             const float* __restrict__ proj_b,
                                             float* __restrict__ out) {
    const int b = blockIdx.z;
    const int warp = threadIdx.x >> 5, lane = threadIdx.x & 31;
    const int wx0 = blockIdx.x * 128;
    const int px0 = wx0 + lane * 4;
    const int y0 = blockIdx.y * 32 + warp * 4;

    const float* __restrict__ xb = x + (size_t)b * 3 * N_PIX;

    const bool is_e = (lane == 0) | (lane == 31);
    const int ex = (lane == 0) ? wx0 - 1 : wx0 + 128;
    const bool ex_ok = (unsigned)ex < (unsigned)W_IMG;

    float cw[9], dw[27];
#pragma unroll
    for (int i = 0; i < 9; i++) cw[i] = kC[i];
#pragma unroll
    for (int i = 0; i < 27; i++) dw[i] = kD[i];

    float m[9];
#pragma unroll
    for (int i = 0; i < 9; i++) m[i] = g_M[b][i];
    const float b0 = proj_b[0], b1 = proj_b[1], b2 = proj_b[2];

    float a0[3][4], a1[3][4], a2[3][4];
#pragma unroll
    for (int c = 0; c < 3; c++)
#pragma unroll
        for (int j = 0; j < 4; j++) { a0[c][j] = a1[c][j] = a2[c][j] = 0.f; }

#pragma unroll
    for (int iy = 0; iy < 6; iy++) {
        const int yin = y0 + iy - 1;
        const bool yok = (unsigned)yin < (unsigned)W_IMG;

        float hm[3][4];
#pragma unroll
        for (int c = 0; c < 3; c++)
#pragma unroll
            for (int j = 0; j < 4; j++) hm[c][j] = 0.f;

        if (yok) {
            const float4* p4 = (const float4*)(xb + (size_t)(yin * W_IMG + px0) * 3);
            float4 v0 = p4[0], v1 = p4[1], v2 = p4[2];
            float g[4][3] = {{v0.x, v0.y, v0.z}, {v0.w, v1.x, v1.y},
                             {v1.z, v1.w, v2.x}, {v2.y, v2.z, v2.w}};
#pragma unroll
            for (int j = 0; j < 4; j++)
#pragma unroll
                for (int c = 0; c < 3; c++)
                    hm[c][j] = cw[c * 3] * g[j][0] + cw[c * 3 + 1] * g[j][1] + cw[c * 3 + 2] * g[j][2];
        }
        float he[3] = {0.f, 0.f, 0.f};
        if (yok && is_e && ex_ok) {
            const float* pe = xb + (size_t)(yin * W_IMG + ex) * 3;
            float g0 = pe[0], g1 = pe[1], g2 = pe[2];
#pragma unroll
            for (int c = 0; c < 3; c++)
                he[c] = cw[c * 3] * g0 + cw[c * 3 + 1] * g1 + cw[c * 3 + 2] * g2;
        }
        float hl[3], hr[3];
#pragma unroll
        for (int c = 0; c < 3; c++) {
            hl[c] = __shfl_up_sync(0xffffffffu, hm[c][3], 1);
            hr[c] = __shfl_down_sync(0xffffffffu, hm[c][0], 1);
            if (lane == 0) hl[c] = he[c];
            if (lane == 31) hr[c] = he[c];
        }
#pragma unroll
        for (int c = 0; c < 3; c++)
#pragma unroll
            for (int j = 0; j < 4; j++) {
                float L = j ? hm[c][j - 1] : hl[c];
                float M_ = hm[c][j];
                float R = (j < 3) ? hm[c][j + 1] : hr[c];
                a0[c][j] += dw[c * 9 + 6] * L + dw[c * 9 + 7] * M_ + dw[c * 9 + 8] * R;
                a1[c][j] += dw[c * 9 + 3] * L + dw[c * 9 + 4] * M_ + dw[c * 9 + 5] * R;
                a2[c][j] += dw[c * 9 + 0] * L + dw[c * 9 + 1] * M_ + dw[c * 9 + 2] * R;
            }
        if (iy >= 2) {
            const int yout = y0 + iy - 2;
            float o[12];
#pragma unroll
            for (int j = 0; j < 4; j++) {
                float k0 = a0[0][j], k1 = a0[1][j], k2 = a0[2][j];
                o[j * 3 + 0] = m[0] * k0 + m[1] * k1 + m[2] * k2 + b0;
                o[j * 3 + 1] = m[3] * k0 + m[4] * k1 + m[5] * k2 + b1;
                o[j * 3 + 2] = m[6] * k0 + m[7] * k1 + m[8] * k2 + b2;
            }
            float4* q4 = (float4*)(out + ((size_t)b * N_PIX + (size_t)yout * W_IMG + px0) * 3);
            q4[0] = make_float4(o[0], o[1], o[2], o[3]);
            q4[1] = make_float4(o[4], o[5], o[6], o[7]);
            q4[2] = make_float4(o[8], o[9], o[10], o[11]);
        }
        // rotate EVERY input row
#pragma unroll
        for (int c = 0; c < 3; c++)
#pragma unroll
            for (int j = 0; j < 4; j++) {
                a0[c][j] = a1[c][j];
                a1[c][j] = a2[c][j];
                a2[c][j] = 0.f;
            }
    }
}

extern "C" void kernel_launch(void* const* d_in, const int* in_sizes, int n_in,
                              void* d_out, int out_size) {
    const float* x     = (const float*)d_in[0];
    const float* fhigh = (const float*)d_in[1];
    const float* qCw   = (const float*)d_in[2];
    const float* qdw   = (const float*)d_in[3];
    const float* kCw   = (const float*)d_in[4];
    const float* kdw   = (const float*)d_in[5];
    const float* projw = (const float*)d_in[6];
    const float* projb = (const float*)d_in[7];
    const float* temp  = (const float*)d_in[8];
    float* out = (float*)d_out;

    int B = in_sizes[0] / (N_PIX * 3);
    if (B > MAXB) B = MAXB;

    k_zero<<<1, 128>>>();
    dim3 grid(W_IMG / 128, W_IMG / 32, B);
    k_stats<<<grid, NTH>>>(x, fhigh, qCw, qdw, kCw, kdw);
    k_attn<<<1, 1>>>(projw, temp, B);
    k_out<<<grid, NTH>>>(x, kCw, kdw, projb, out);
}